// round 2
// baseline (speedup 1.0000x reference)
#include <cuda_runtime.h>
#include <cuda_bf16.h>
#include <cstdint>

// Problem constants (shapes fixed by the reference)
#define IN_F   128
#define OUT_F  64
#define MAX_NODES 100000

// Scratch: support = vertex @ W, [N_NODES, OUT_F] fp32 (25.6 MB)
__device__ float g_support[(size_t)MAX_NODES * OUT_F];

// ---------------------------------------------------------------------------
// Kernel 1: out[n][c] = bias[c]   (fold bias into init; out is 0xAA-poisoned)
// ---------------------------------------------------------------------------
__global__ void init_out_kernel(float* __restrict__ out,
                                const float* __restrict__ bias,
                                int total4) {
    int i = blockIdx.x * blockDim.x + threadIdx.x;
    if (i >= total4) return;
    // OUT_F = 64 floats = 16 float4 per row
    const float4* b4 = (const float4*)bias;
    float4 v = b4[i & 15];
    ((float4*)out)[i] = v;
}

// ---------------------------------------------------------------------------
// Kernel 2: support = vertex @ W
// One warp per row. W (128x64 fp32 = 32 KB) staged in shared as float2[128][32].
// Each lane keeps 4 A-elements in registers; broadcast via shfl; each lane
// accumulates 2 output columns.
// ---------------------------------------------------------------------------
__global__ __launch_bounds__(256) void gemm_kernel(
    const float* __restrict__ A,   // [N, 128]
    const float* __restrict__ W,   // [128, 64]
    float* __restrict__ S,         // [N, 64]
    int nRows) {
    __shared__ float2 Ws[IN_F][OUT_F / 2];   // 32 KB

    for (int i = threadIdx.x; i < IN_F * (OUT_F / 2); i += blockDim.x) {
        int k  = i >> 5;          // 0..127
        int c2 = i & 31;          // 0..31
        Ws[k][c2] = *(const float2*)(W + k * OUT_F + c2 * 2);
    }
    __syncthreads();

    int warp = blockIdx.x * (blockDim.x >> 5) + (threadIdx.x >> 5);
    int lane = threadIdx.x & 31;
    if (warp >= nRows) return;

    const float* arow = A + (size_t)warp * IN_F;
    float ar[4];
#pragma unroll
    for (int j = 0; j < 4; j++) ar[j] = arow[j * 32 + lane];

    float accx = 0.f, accy = 0.f;
#pragma unroll
    for (int j = 0; j < 4; j++) {
#pragma unroll
        for (int t = 0; t < 32; t++) {
            float a  = __shfl_sync(0xffffffffu, ar[j], t);
            float2 w = Ws[j * 32 + t][lane];
            accx = fmaf(a, w.x, accx);
            accy = fmaf(a, w.y, accy);
        }
    }
    *(float2*)(S + (size_t)warp * OUT_F + lane * 2) = make_float2(accx, accy);
}

// ---------------------------------------------------------------------------
// Kernel 3: COO scatter-add with vector reductions.
// 16 threads per edge; each thread owns one float4 chunk (16 B).
// Gather support[col] (256 B contiguous, coalesced), scale by edge_val,
// red.global.add.v4.f32 into out[row] (16-B aligned).
// ---------------------------------------------------------------------------
__global__ __launch_bounds__(256) void scatter_kernel(
    const int*   __restrict__ erow,
    const int*   __restrict__ ecol,
    const float* __restrict__ eval_,
    const float* __restrict__ S,
    float*       __restrict__ out,
    int nE) {
    int gid = blockIdx.x * blockDim.x + threadIdx.x;
    int e = gid >> 4;
    if (e >= nE) return;
    int c4 = (gid & 15) << 2;      // float offset: 0,4,...,60

    int   r = __ldg(erow + e);
    int   c = __ldg(ecol + e);
    float v = __ldg(eval_ + e);

    float4 s = *(const float4*)(S + (size_t)c * OUT_F + c4);
    float4 m;
    m.x = s.x * v; m.y = s.y * v; m.z = s.z * v; m.w = s.w * v;

    float* dst = out + (size_t)r * OUT_F + c4;
    asm volatile("red.global.add.v4.f32 [%0], {%1, %2, %3, %4};"
                 :: "l"(dst), "f"(m.x), "f"(m.y), "f"(m.z), "f"(m.w)
                 : "memory");
}

// ---------------------------------------------------------------------------
// launch
// ---------------------------------------------------------------------------
extern "C" void kernel_launch(void* const* d_in, const int* in_sizes, int n_in,
                              void* d_out, int out_size) {
    const float* vertex  = (const float*)d_in[0];   // [N, 128]
    const int*   erow    = (const int*)  d_in[1];   // [E]
    const int*   ecol    = (const int*)  d_in[2];   // [E]
    const float* eval_   = (const float*)d_in[3];   // [E]
    const float* weights = (const float*)d_in[4];   // [128, 64]
    const float* bias    = (const float*)d_in[5];   // [64]
    float*       out     = (float*)d_out;           // [N, 64]

    int nNodes = in_sizes[0] / IN_F;
    int nE     = in_sizes[1];

    float* support = nullptr;
    cudaGetSymbolAddress((void**)&support, g_support);

    // out[n][c] = bias[c]
    {
        int total4 = nNodes * (OUT_F / 4);
        init_out_kernel<<<(total4 + 255) / 256, 256>>>(out, bias, total4);
    }

    // support = vertex @ W
    {
        int warpsPerBlock = 256 / 32;
        int blocks = (nNodes + warpsPerBlock - 1) / warpsPerBlock;
        gemm_kernel<<<blocks, 256>>>(vertex, weights, support, nNodes);
    }

    // scatter-add: 16 threads per edge
    {
        unsigned int total = (unsigned int)nE * 16u;
        unsigned int blocks = (total + 255u) / 256u;
        scatter_kernel<<<blocks, 256>>>(erow, ecol, eval_, support, out, nE);
    }
}

// round 4
// speedup vs baseline: 1.0541x; 1.0541x over previous
#include <cuda_runtime.h>
#include <cuda_bf16.h>
#include <cstdint>

#define IN_F   128
#define OUT_F  64
#define MAX_NODES 100000
#define MAX_EDGES 1600000
#define SCAN_B 1024          // elements per scan block
#define MAX_SCAN_BLOCKS 128  // ceil(100000/1024)=98

// Scratch (device globals; no allocation allowed)
__device__ float g_support[(size_t)MAX_NODES * OUT_F];   // vertex @ W
__device__ int   g_cnt[MAX_NODES];                       // per-row degree
__device__ int   g_start[MAX_NODES];                     // CSR row starts
__device__ int   g_cursor[MAX_NODES];                    // fill cursors
__device__ int   g_bsums[MAX_SCAN_BLOCKS];               // scan block sums
__device__ int2  g_bin[MAX_EDGES];                       // (col, val-bits) binned by row

// ---------------------------------------------------------------------------
// zero counts
// ---------------------------------------------------------------------------
__global__ void zero_kernel(int* __restrict__ p, int n) {
    int i = blockIdx.x * blockDim.x + threadIdx.x;
    if (i < n) p[i] = 0;
}

// ---------------------------------------------------------------------------
// histogram of destination rows
// ---------------------------------------------------------------------------
__global__ void count_kernel(const int* __restrict__ erow,
                             int* __restrict__ cnt, int nE) {
    int e = blockIdx.x * blockDim.x + threadIdx.x;
    if (e < nE) atomicAdd(&cnt[__ldg(erow + e)], 1);
}

// ---------------------------------------------------------------------------
// scan phase 1: per-block exclusive scan (1024 elems/block) + block totals
// ---------------------------------------------------------------------------
__global__ __launch_bounds__(SCAN_B) void scan_block_kernel(
    const int* __restrict__ cnt, int* __restrict__ start,
    int* __restrict__ bsums, int n) {
    __shared__ int sh[SCAN_B];
    int tid = threadIdx.x;
    int gid = blockIdx.x * SCAN_B + tid;
    int v = (gid < n) ? cnt[gid] : 0;
    sh[tid] = v;
    __syncthreads();
    for (int off = 1; off < SCAN_B; off <<= 1) {
        int t = (tid >= off) ? sh[tid - off] : 0;
        __syncthreads();
        sh[tid] += t;
        __syncthreads();
    }
    if (gid < n) start[gid] = sh[tid] - v;       // exclusive
    if (tid == SCAN_B - 1) bsums[blockIdx.x] = sh[tid];
}

// ---------------------------------------------------------------------------
// scan phase 2: exclusive scan of block sums (nb <= 128), one block
// ---------------------------------------------------------------------------
__global__ void scan_sums_kernel(int* __restrict__ bsums, int nb) {
    __shared__ int sh[MAX_SCAN_BLOCKS];
    int tid = threadIdx.x;
    int v = (tid < nb) ? bsums[tid] : 0;
    sh[tid] = v;
    __syncthreads();
    for (int off = 1; off < MAX_SCAN_BLOCKS; off <<= 1) {
        int t = (tid >= off) ? sh[tid - off] : 0;
        __syncthreads();
        sh[tid] += t;
        __syncthreads();
    }
    if (tid < nb) bsums[tid] = sh[tid] - v;      // exclusive
}

// ---------------------------------------------------------------------------
// scan phase 3: add block offsets, init cursors
// ---------------------------------------------------------------------------
__global__ void add_offsets_kernel(int* __restrict__ start,
                                   const int* __restrict__ bsums,
                                   int* __restrict__ cursor, int n) {
    int gid = blockIdx.x * blockDim.x + threadIdx.x;
    if (gid < n) {
        int s = start[gid] + bsums[gid >> 10];
        start[gid] = s;
        cursor[gid] = s;
    }
}

// ---------------------------------------------------------------------------
// fill bins: edge e -> slot atomically claimed within its row segment
// ---------------------------------------------------------------------------
__global__ void fill_kernel(const int* __restrict__ erow,
                            const int* __restrict__ ecol,
                            const float* __restrict__ eval_,
                            int* __restrict__ cursor,
                            int2* __restrict__ bin, int nE) {
    int e = blockIdx.x * blockDim.x + threadIdx.x;
    if (e >= nE) return;
    int r = __ldg(erow + e);
    int pos = atomicAdd(&cursor[r], 1);
    bin[pos] = make_int2(__ldg(ecol + e), __float_as_int(__ldg(eval_ + e)));
}

// ---------------------------------------------------------------------------
// GEMM: support = vertex @ W  (warp per row, W staged in shared)
// ---------------------------------------------------------------------------
__global__ __launch_bounds__(256) void gemm_kernel(
    const float* __restrict__ A, const float* __restrict__ W,
    float* __restrict__ S, int nRows) {
    __shared__ float2 Ws[IN_F][OUT_F / 2];   // 32 KB

    for (int i = threadIdx.x; i < IN_F * (OUT_F / 2); i += blockDim.x) {
        int k = i >> 5, c2 = i & 31;
        Ws[k][c2] = *(const float2*)(W + k * OUT_F + c2 * 2);
    }
    __syncthreads();

    int warp = blockIdx.x * (blockDim.x >> 5) + (threadIdx.x >> 5);
    int lane = threadIdx.x & 31;
    if (warp >= nRows) return;

    const float* arow = A + (size_t)warp * IN_F;
    float ar[4];
#pragma unroll
    for (int j = 0; j < 4; j++) ar[j] = arow[j * 32 + lane];

    float accx = 0.f, accy = 0.f;
#pragma unroll
    for (int j = 0; j < 4; j++) {
#pragma unroll
        for (int t = 0; t < 32; t++) {
            float a  = __shfl_sync(0xffffffffu, ar[j], t);
            float2 w = Ws[j * 32 + t][lane];
            accx = fmaf(a, w.x, accx);
            accy = fmaf(a, w.y, accy);
        }
    }
    *(float2*)(S + (size_t)warp * OUT_F + lane * 2) = make_float2(accx, accy);
}

// ---------------------------------------------------------------------------
// Row-centric SpMM: one warp per output row; register accumulation;
// single non-atomic write; bias folded in.
// ---------------------------------------------------------------------------
__global__ __launch_bounds__(256) void spmm_kernel(
    const int*  __restrict__ start,
    const int*  __restrict__ cnt,
    const int2* __restrict__ bin,
    const float* __restrict__ S,
    const float* __restrict__ bias,
    float* __restrict__ out, int nRows) {
    int warp = blockIdx.x * (blockDim.x >> 5) + (threadIdx.x >> 5);
    int lane = threadIdx.x & 31;
    if (warp >= nRows) return;

    int s0  = __ldg(start + warp);
    int deg = __ldg(cnt + warp);

    float2 acc;
    acc.x = __ldg(bias + lane * 2);
    acc.y = __ldg(bias + lane * 2 + 1);

    for (int base = 0; base < deg; base += 32) {
        int i = base + lane;
        int2 ed = make_int2(0, 0);
        if (i < deg) ed = __ldg(bin + s0 + i);
        int m = min(32, deg - base);
        for (int j = 0; j < m; j++) {
            int   cj = __shfl_sync(0xffffffffu, ed.x, j);
            float vj = __int_as_float(__shfl_sync(0xffffffffu, ed.y, j));
            float2 sv = *(const float2*)(S + (size_t)cj * OUT_F + lane * 2);
            acc.x = fmaf(vj, sv.x, acc.x);
            acc.y = fmaf(vj, sv.y, acc.y);
        }
    }
    *(float2*)(out + (size_t)warp * OUT_F + lane * 2) = acc;
}

// ---------------------------------------------------------------------------
// launch
// ---------------------------------------------------------------------------
extern "C" void kernel_launch(void* const* d_in, const int* in_sizes, int n_in,
                              void* d_out, int out_size) {
    const float* vertex  = (const float*)d_in[0];   // [N, 128]
    const int*   erow    = (const int*)  d_in[1];   // [E]
    const int*   ecol    = (const int*)  d_in[2];   // [E]
    const float* eval_   = (const float*)d_in[3];   // [E]
    const float* weights = (const float*)d_in[4];   // [128, 64]
    const float* bias    = (const float*)d_in[5];   // [64]
    float*       out     = (float*)d_out;           // [N, 64]

    int nNodes = in_sizes[0] / IN_F;
    int nE     = in_sizes[1];

    float* support; cudaGetSymbolAddress((void**)&support, g_support);
    int*   cnt;     cudaGetSymbolAddress((void**)&cnt,     g_cnt);
    int*   start;   cudaGetSymbolAddress((void**)&start,   g_start);
    int*   cursor;  cudaGetSymbolAddress((void**)&cursor,  g_cursor);
    int*   bsums;   cudaGetSymbolAddress((void**)&bsums,   g_bsums);
    int2*  bin;     cudaGetSymbolAddress((void**)&bin,     g_bin);

    int nb = (nNodes + SCAN_B - 1) / SCAN_B;

    // 1) zero counts
    zero_kernel<<<(nNodes + 255) / 256, 256>>>(cnt, nNodes);
    // 2) histogram
    count_kernel<<<(nE + 511) / 512, 512>>>(erow, cnt, nE);
    // 3) GEMM (independent; interleave to keep SMs busy between dep chains)
    {
        int blocks = (nNodes + 7) / 8;
        gemm_kernel<<<blocks, 256>>>(vertex, weights, support, nNodes);
    }
    // 4) scan
    scan_block_kernel<<<nb, SCAN_B>>>(cnt, start, bsums, nNodes);
    scan_sums_kernel<<<1, MAX_SCAN_BLOCKS>>>(bsums, nb);
    add_offsets_kernel<<<(nNodes + 255) / 256, 256>>>(start, bsums, cursor, nNodes);
    // 5) fill bins
    fill_kernel<<<(nE + 511) / 512, 512>>>(erow, ecol, eval_, cursor, bin, nE);
    // 6) row-centric SpMM (+bias)
    {
        int blocks = (nNodes + 7) / 8;
        spmm_kernel<<<blocks, 256>>>(start, cnt, bin, support, bias, out, nNodes);
    }
}

// round 5
// speedup vs baseline: 1.9367x; 1.8373x over previous
#include <cuda_runtime.h>
#include <cuda_bf16.h>
#include <cstdint>

#define IN_F   128
#define OUT_F  64
#define MAX_NODES 100000
#define MAX_EDGES 1600000
#define SCAN_B 1024
#define MAX_SCAN_BLOCKS 128
#define GEMM_TM 128
#define GEMM_TK 16
#define AS_PAD 132   // 128 + 4 to break store bank conflicts

// Scratch (device globals; no allocation allowed)
__device__ float g_support[(size_t)MAX_NODES * OUT_F];
__device__ int   g_cnt[MAX_NODES];
__device__ int   g_start[MAX_NODES];
__device__ int   g_cursor[MAX_NODES];
__device__ int   g_bsums[MAX_SCAN_BLOCKS];
__device__ int2  g_bin[MAX_EDGES];

// ---------------------------------------------------------------------------
__global__ void zero_kernel(int* __restrict__ p, int n) {
    int i = blockIdx.x * blockDim.x + threadIdx.x;
    if (i < n) p[i] = 0;
}

__global__ void count_kernel(const int* __restrict__ erow,
                             int* __restrict__ cnt, int nE) {
    int e = blockIdx.x * blockDim.x + threadIdx.x;
    if (e < nE) atomicAdd(&cnt[__ldg(erow + e)], 1);
}

__global__ __launch_bounds__(SCAN_B) void scan_block_kernel(
    const int* __restrict__ cnt, int* __restrict__ start,
    int* __restrict__ bsums, int n) {
    __shared__ int sh[SCAN_B];
    int tid = threadIdx.x;
    int gid = blockIdx.x * SCAN_B + tid;
    int v = (gid < n) ? cnt[gid] : 0;
    sh[tid] = v;
    __syncthreads();
    for (int off = 1; off < SCAN_B; off <<= 1) {
        int t = (tid >= off) ? sh[tid - off] : 0;
        __syncthreads();
        sh[tid] += t;
        __syncthreads();
    }
    if (gid < n) start[gid] = sh[tid] - v;
    if (tid == SCAN_B - 1) bsums[blockIdx.x] = sh[tid];
}

__global__ void scan_sums_kernel(int* __restrict__ bsums, int nb) {
    __shared__ int sh[MAX_SCAN_BLOCKS];
    int tid = threadIdx.x;
    int v = (tid < nb) ? bsums[tid] : 0;
    sh[tid] = v;
    __syncthreads();
    for (int off = 1; off < MAX_SCAN_BLOCKS; off <<= 1) {
        int t = (tid >= off) ? sh[tid - off] : 0;
        __syncthreads();
        sh[tid] += t;
        __syncthreads();
    }
    if (tid < nb) bsums[tid] = sh[tid] - v;
}

__global__ void add_offsets_kernel(int* __restrict__ start,
                                   const int* __restrict__ bsums,
                                   int* __restrict__ cursor, int n) {
    int gid = blockIdx.x * blockDim.x + threadIdx.x;
    if (gid < n) {
        int s = start[gid] + bsums[gid >> 10];
        start[gid] = s;
        cursor[gid] = s;
    }
}

__global__ void fill_kernel(const int* __restrict__ erow,
                            const int* __restrict__ ecol,
                            const float* __restrict__ eval_,
                            int* __restrict__ cursor,
                            int2* __restrict__ bin, int nE) {
    int e = blockIdx.x * blockDim.x + threadIdx.x;
    if (e >= nE) return;
    int r = __ldg(erow + e);
    int pos = atomicAdd(&cursor[r], 1);
    bin[pos] = make_int2(__ldg(ecol + e), __float_as_int(__ldg(eval_ + e)));
}

// ---------------------------------------------------------------------------
// Register-tiled GEMM: block = 128 rows x 64 cols, 256 threads,
// each thread computes 8 rows x 4 cols. FMA:LDS issue ratio ~ 32:3.
// ---------------------------------------------------------------------------
__global__ __launch_bounds__(256) void gemm_kernel(
    const float* __restrict__ A,   // [N, 128]
    const float* __restrict__ W,   // [128, 64]
    float* __restrict__ S,         // [N, 64]
    int n) {
    __shared__ float As[GEMM_TK][AS_PAD];        // k-major A tile
    __shared__ float Ws[GEMM_TK][OUT_F];         // k-major W tile

    int tid = threadIdx.x;
    int tx = tid & 15;          // col group: cols tx*4 .. tx*4+3
    int ty = tid >> 4;          // row group: rows ty*8 .. ty*8+7
    int r0 = blockIdx.x * GEMM_TM;

    float acc[8][4];
#pragma unroll
    for (int i = 0; i < 8; i++)
#pragma unroll
        for (int c = 0; c < 4; c++) acc[i][c] = 0.f;

    for (int kk = 0; kk < IN_F; kk += GEMM_TK) {
        // Stage A tile (128 rows x 16 k), transposed to k-major.
#pragma unroll
        for (int l = 0; l < 2; l++) {
            int idx = tid + l * 256;            // 0..511
            int row = idx >> 2;                 // 0..127
            int f4  = idx & 3;                  // 0..3
            int gr  = r0 + row; if (gr >= n) gr = n - 1;
            float4 a = __ldg((const float4*)(A + (size_t)gr * IN_F + kk + f4 * 4));
            As[f4 * 4 + 0][row] = a.x;
            As[f4 * 4 + 1][row] = a.y;
            As[f4 * 4 + 2][row] = a.z;
            As[f4 * 4 + 3][row] = a.w;
        }
        // Stage W tile (16 k x 64 cols): 256 float4, 1 per thread.
        {
            int krow = tid >> 4;                // 0..15
            int f4   = tid & 15;                // 0..15
            float4 w = __ldg((const float4*)(W + (size_t)(kk + krow) * OUT_F + f4 * 4));
            *(float4*)&Ws[krow][f4 * 4] = w;
        }
        __syncthreads();

#pragma unroll
        for (int k = 0; k < GEMM_TK; k++) {
            float4 w = *(const float4*)&Ws[k][tx * 4];
#pragma unroll
            for (int i = 0; i < 8; i++) {
                float a = As[k][ty * 8 + i];
                acc[i][0] = fmaf(a, w.x, acc[i][0]);
                acc[i][1] = fmaf(a, w.y, acc[i][1]);
                acc[i][2] = fmaf(a, w.z, acc[i][2]);
                acc[i][3] = fmaf(a, w.w, acc[i][3]);
            }
        }
        __syncthreads();
    }

#pragma unroll
    for (int i = 0; i < 8; i++) {
        int r = r0 + ty * 8 + i;
        if (r < n) {
            *(float4*)(S + (size_t)r * OUT_F + tx * 4) =
                make_float4(acc[i][0], acc[i][1], acc[i][2], acc[i][3]);
        }
    }
}

// ---------------------------------------------------------------------------
// Row-centric SpMM with MLP=8: zero-padded edge batches let the inner
// 8-edge group fully unroll (dummy edges have val=0 -> contribute nothing).
// ---------------------------------------------------------------------------
__global__ __launch_bounds__(256) void spmm_kernel(
    const int*  __restrict__ start,
    const int*  __restrict__ cnt,
    const int2* __restrict__ bin,
    const float* __restrict__ S,
    const float* __restrict__ bias,
    float* __restrict__ out, int nRows) {
    int warp = blockIdx.x * (blockDim.x >> 5) + (threadIdx.x >> 5);
    int lane = threadIdx.x & 31;
    if (warp >= nRows) return;

    int s0  = __ldg(start + warp);
    int deg = __ldg(cnt + warp);

    float2 acc;
    acc.x = __ldg(bias + lane * 2);
    acc.y = __ldg(bias + lane * 2 + 1);

    for (int base = 0; base < deg; base += 32) {
        int i = base + lane;
        // zero-pad: col 0, val 0.0f beyond deg (adds exactly 0)
        int2 ed = (i < deg) ? __ldg(bin + s0 + i) : make_int2(0, 0);
        int m = deg - base; if (m > 32) m = 32;
        for (int j0 = 0; j0 < m; j0 += 8) {
            float2 sv[8];
            float  vf[8];
#pragma unroll
            for (int j = 0; j < 8; j++) {
                int jj = j0 + j;
                int   cj = __shfl_sync(0xffffffffu, ed.x, jj);
                vf[j] = __int_as_float(__shfl_sync(0xffffffffu, ed.y, jj));
                sv[j] = *(const float2*)(S + (size_t)cj * OUT_F + lane * 2);
            }
#pragma unroll
            for (int j = 0; j < 8; j++) {
                acc.x = fmaf(vf[j], sv[j].x, acc.x);
                acc.y = fmaf(vf[j], sv[j].y, acc.y);
            }
        }
    }
    *(float2*)(out + (size_t)warp * OUT_F + lane * 2) = acc;
}

// ---------------------------------------------------------------------------
extern "C" void kernel_launch(void* const* d_in, const int* in_sizes, int n_in,
                              void* d_out, int out_size) {
    const float* vertex  = (const float*)d_in[0];
    const int*   erow    = (const int*)  d_in[1];
    const int*   ecol    = (const int*)  d_in[2];
    const float* eval_   = (const float*)d_in[3];
    const float* weights = (const float*)d_in[4];
    const float* bias    = (const float*)d_in[5];
    float*       out     = (float*)d_out;

    int nNodes = in_sizes[0] / IN_F;
    int nE     = in_sizes[1];

    float* support; cudaGetSymbolAddress((void**)&support, g_support);
    int*   cnt;     cudaGetSymbolAddress((void**)&cnt,     g_cnt);
    int*   start;   cudaGetSymbolAddress((void**)&start,   g_start);
    int*   cursor;  cudaGetSymbolAddress((void**)&cursor,  g_cursor);
    int*   bsums;   cudaGetSymbolAddress((void**)&bsums,   g_bsums);
    int2*  bin;     cudaGetSymbolAddress((void**)&bin,     g_bin);

    int nb = (nNodes + SCAN_B - 1) / SCAN_B;

    zero_kernel<<<(nNodes + 255) / 256, 256>>>(cnt, nNodes);
    count_kernel<<<(nE + 511) / 512, 512>>>(erow, cnt, nE);
    gemm_kernel<<<(nNodes + GEMM_TM - 1) / GEMM_TM, 256>>>(vertex, weights, support, nNodes);
    scan_block_kernel<<<nb, SCAN_B>>>(cnt, start, bsums, nNodes);
    scan_sums_kernel<<<1, MAX_SCAN_BLOCKS>>>(bsums, nb);
    add_offsets_kernel<<<(nNodes + 255) / 256, 256>>>(start, bsums, cursor, nNodes);
    fill_kernel<<<(nE + 511) / 512, 512>>>(erow, ecol, eval_, cursor, bin, nE);
    spmm_kernel<<<(nNodes + 7) / 8, 256>>>(start, cnt, bin, support, bias, out, nNodes);
}

// round 6
// speedup vs baseline: 2.0279x; 1.0471x over previous
#include <cuda_runtime.h>
#include <cuda_bf16.h>
#include <cstdint>

#define IN_F   128
#define OUT_F  64
#define MAX_NODES 100000
#define MAX_EDGES 1600000
#define SCAN_B 1024
#define MAX_SCAN_BLOCKS 128
#define GEMM_TM 128
#define GEMM_TK 16
#define AS_PAD 132   // 128 + 4 to break store bank conflicts

// Scratch (device globals; no allocation allowed)
__device__ float g_support[(size_t)MAX_NODES * OUT_F];
__device__ int   g_cnt[MAX_NODES];
__device__ int   g_start[MAX_NODES];
__device__ int   g_cursor[MAX_NODES];
__device__ int   g_bsums[MAX_SCAN_BLOCKS];
__device__ int2  g_bin[MAX_EDGES];

// ---------------------------------------------------------------------------
__global__ void count_kernel(const int* __restrict__ erow,
                             int* __restrict__ cnt, int nE) {
    int e = blockIdx.x * blockDim.x + threadIdx.x;
    if (e < nE) atomicAdd(&cnt[__ldg(erow + e)], 1);
}

// shfl-based per-block exclusive scan (1024 elems/block) + block totals
__global__ __launch_bounds__(SCAN_B) void scan_block_kernel(
    const int* __restrict__ cnt, int* __restrict__ start,
    int* __restrict__ bsums, int n) {
    __shared__ int wsum[32];
    int tid = threadIdx.x;
    int gid = blockIdx.x * SCAN_B + tid;
    int lane = tid & 31, wid = tid >> 5;

    int v = (gid < n) ? cnt[gid] : 0;
    int x = v;                               // inclusive warp scan
#pragma unroll
    for (int o = 1; o < 32; o <<= 1) {
        int t = __shfl_up_sync(0xffffffffu, x, o);
        if (lane >= o) x += t;
    }
    if (lane == 31) wsum[wid] = x;
    __syncthreads();
    if (wid == 0) {
        int s = wsum[lane];
#pragma unroll
        for (int o = 1; o < 32; o <<= 1) {
            int t = __shfl_up_sync(0xffffffffu, s, o);
            if (lane >= o) s += t;
        }
        wsum[lane] = s;
    }
    __syncthreads();
    int excl = x - v + (wid > 0 ? wsum[wid - 1] : 0);
    if (gid < n) start[gid] = excl;
    if (tid == SCAN_B - 1) bsums[blockIdx.x] = excl + v;
}

__global__ void scan_sums_kernel(int* __restrict__ bsums, int nb) {
    __shared__ int sh[MAX_SCAN_BLOCKS];
    int tid = threadIdx.x;
    int v = (tid < nb) ? bsums[tid] : 0;
    sh[tid] = v;
    __syncthreads();
    for (int off = 1; off < MAX_SCAN_BLOCKS; off <<= 1) {
        int t = (tid >= off) ? sh[tid - off] : 0;
        __syncthreads();
        sh[tid] += t;
        __syncthreads();
    }
    if (tid < nb) bsums[tid] = sh[tid] - v;
}

__global__ void add_offsets_kernel(int* __restrict__ start,
                                   const int* __restrict__ bsums,
                                   int* __restrict__ cursor, int n) {
    int gid = blockIdx.x * blockDim.x + threadIdx.x;
    if (gid < n) {
        int s = start[gid] + bsums[gid >> 10];
        start[gid] = s;
        cursor[gid] = s;
    }
}

// ---------------------------------------------------------------------------
// Fused heterogeneous kernel:
//   blocks [0, nGemmBlocks)      : register-tiled GEMM (FMA-bound)
//   blocks [nGemmBlocks, end)    : fill bins (atomic/scatter-bound)
// The two halves use disjoint pipes and overlap on the chip, hiding GEMM
// behind fill's memory latency.
// ---------------------------------------------------------------------------
__global__ __launch_bounds__(256) void gemm_fill_kernel(
    const float* __restrict__ A,   // [N, 128]
    const float* __restrict__ W,   // [128, 64]
    float* __restrict__ S,         // [N, 64]
    int n, int nGemmBlocks,
    const int*   __restrict__ erow,
    const int*   __restrict__ ecol,
    const float* __restrict__ eval_,
    int*  __restrict__ cursor,
    int2* __restrict__ bin, int nE) {
    __shared__ float As[GEMM_TK][AS_PAD];
    __shared__ float Ws[GEMM_TK][OUT_F];

    int tid = threadIdx.x;

    if (blockIdx.x >= nGemmBlocks) {
        // ---- fill half ----
        int e = (blockIdx.x - nGemmBlocks) * 256 + tid;
        if (e < nE) {
            int r = __ldg(erow + e);
            int pos = atomicAdd(&cursor[r], 1);
            bin[pos] = make_int2(__ldg(ecol + e), __float_as_int(__ldg(eval_ + e)));
        }
        return;
    }

    // ---- GEMM half ----
    int tx = tid & 15;          // col group
    int ty = tid >> 4;          // row group
    int r0 = blockIdx.x * GEMM_TM;

    float acc[8][4];
#pragma unroll
    for (int i = 0; i < 8; i++)
#pragma unroll
        for (int c = 0; c < 4; c++) acc[i][c] = 0.f;

    for (int kk = 0; kk < IN_F; kk += GEMM_TK) {
#pragma unroll
        for (int l = 0; l < 2; l++) {
            int idx = tid + l * 256;
            int row = idx >> 2;
            int f4  = idx & 3;
            int gr  = r0 + row; if (gr >= n) gr = n - 1;
            float4 a = __ldg((const float4*)(A + (size_t)gr * IN_F + kk + f4 * 4));
            As[f4 * 4 + 0][row] = a.x;
            As[f4 * 4 + 1][row] = a.y;
            As[f4 * 4 + 2][row] = a.z;
            As[f4 * 4 + 3][row] = a.w;
        }
        {
            int krow = tid >> 4;
            int f4   = tid & 15;
            float4 w = __ldg((const float4*)(W + (size_t)(kk + krow) * OUT_F + f4 * 4));
            *(float4*)&Ws[krow][f4 * 4] = w;
        }
        __syncthreads();

#pragma unroll
        for (int k = 0; k < GEMM_TK; k++) {
            float4 w = *(const float4*)&Ws[k][tx * 4];
#pragma unroll
            for (int i = 0; i < 8; i++) {
                float a = As[k][ty * 8 + i];
                acc[i][0] = fmaf(a, w.x, acc[i][0]);
                acc[i][1] = fmaf(a, w.y, acc[i][1]);
                acc[i][2] = fmaf(a, w.z, acc[i][2]);
                acc[i][3] = fmaf(a, w.w, acc[i][3]);
            }
        }
        __syncthreads();
    }

#pragma unroll
    for (int i = 0; i < 8; i++) {
        int r = r0 + ty * 8 + i;
        if (r < n) {
            *(float4*)(S + (size_t)r * OUT_F + tx * 4) =
                make_float4(acc[i][0], acc[i][1], acc[i][2], acc[i][3]);
        }
    }
}

// ---------------------------------------------------------------------------
// Row-centric SpMM with MLP=8 (zero-padded batches -> fully unrolled groups)
// ---------------------------------------------------------------------------
__global__ __launch_bounds__(256) void spmm_kernel(
    const int*  __restrict__ start,
    const int*  __restrict__ cnt,
    const int2* __restrict__ bin,
    const float* __restrict__ S,
    const float* __restrict__ bias,
    float* __restrict__ out, int nRows) {
    int warp = blockIdx.x * (blockDim.x >> 5) + (threadIdx.x >> 5);
    int lane = threadIdx.x & 31;
    if (warp >= nRows) return;

    int s0  = __ldg(start + warp);
    int deg = __ldg(cnt + warp);

    float2 acc;
    acc.x = __ldg(bias + lane * 2);
    acc.y = __ldg(bias + lane * 2 + 1);

    for (int base = 0; base < deg; base += 32) {
        int i = base + lane;
        int2 ed = (i < deg) ? __ldg(bin + s0 + i) : make_int2(0, 0);
        int m = deg - base; if (m > 32) m = 32;
        for (int j0 = 0; j0 < m; j0 += 8) {
            float2 sv[8];
            float  vf[8];
#pragma unroll
            for (int j = 0; j < 8; j++) {
                int jj = j0 + j;
                int   cj = __shfl_sync(0xffffffffu, ed.x, jj);
                vf[j] = __int_as_float(__shfl_sync(0xffffffffu, ed.y, jj));
                sv[j] = *(const float2*)(S + (size_t)cj * OUT_F + lane * 2);
            }
#pragma unroll
            for (int j = 0; j < 8; j++) {
                acc.x = fmaf(vf[j], sv[j].x, acc.x);
                acc.y = fmaf(vf[j], sv[j].y, acc.y);
            }
        }
    }
    *(float2*)(out + (size_t)warp * OUT_F + lane * 2) = acc;
}

// ---------------------------------------------------------------------------
extern "C" void kernel_launch(void* const* d_in, const int* in_sizes, int n_in,
                              void* d_out, int out_size) {
    const float* vertex  = (const float*)d_in[0];
    const int*   erow    = (const int*)  d_in[1];
    const int*   ecol    = (const int*)  d_in[2];
    const float* eval_   = (const float*)d_in[3];
    const float* weights = (const float*)d_in[4];
    const float* bias    = (const float*)d_in[5];
    float*       out     = (float*)d_out;

    int nNodes = in_sizes[0] / IN_F;
    int nE     = in_sizes[1];

    float* support; cudaGetSymbolAddress((void**)&support, g_support);
    int*   cnt;     cudaGetSymbolAddress((void**)&cnt,     g_cnt);
    int*   start;   cudaGetSymbolAddress((void**)&start,   g_start);
    int*   cursor;  cudaGetSymbolAddress((void**)&cursor,  g_cursor);
    int*   bsums;   cudaGetSymbolAddress((void**)&bsums,   g_bsums);
    int2*  bin;     cudaGetSymbolAddress((void**)&bin,     g_bin);

    int nb = (nNodes + SCAN_B - 1) / SCAN_B;

    // 1) zero counts (memset node — cheaper than a kernel)
    cudaMemsetAsync(cnt, 0, (size_t)nNodes * sizeof(int), 0);
    // 2) histogram of destination rows
    count_kernel<<<(nE + 511) / 512, 512>>>(erow, cnt, nE);
    // 3) scan -> row starts + cursors
    scan_block_kernel<<<nb, SCAN_B>>>(cnt, start, bsums, nNodes);
    scan_sums_kernel<<<1, MAX_SCAN_BLOCKS>>>(bsums, nb);
    add_offsets_kernel<<<(nNodes + 255) / 256, 256>>>(start, bsums, cursor, nNodes);
    // 4) fused: GEMM (independent) overlapped with bin fill
    {
        int nGemm = (nNodes + GEMM_TM - 1) / GEMM_TM;
        int nFill = (nE + 255) / 256;
        gemm_fill_kernel<<<nGemm + nFill, 256>>>(
            vertex, weights, support, nNodes, nGemm,
            erow, ecol, eval_, cursor, bin, nE);
    }
    // 5) row-centric SpMM (+bias)
    spmm_kernel<<<(nNodes + 7) / 8, 256>>>(start, cnt, bin, support, bias, out, nNodes);
}